// round 1
// baseline (speedup 1.0000x reference)
#include <cuda_runtime.h>
#include <math.h>

// LSTM: T=512, B=64, I=H=512.  out[t,b,h] = h_t.
// Kernel 1: x_proj[t][g][b] = x @ W_ih^T + (b_ih + b_hh)   (transposed store)
// Kernel 2: persistent 128-CTA recurrent kernel with software grid barrier.

#define Tq 512
#define Bq 64
#define Hq 512
#define G4 2048
#define REC_NCTA 128
#define HSTRIDE 516                      // padded h row (bank-conflict-free)
#define REC_SMEM ((16 * 512 + Bq * HSTRIDE) * 4)

typedef unsigned long long ull;

// 256 MB scratch for x_proj, layout [T][4H][B]
__device__ float g_xp[(size_t)Tq * G4 * Bq];
__device__ unsigned g_count = 0;
__device__ volatile unsigned g_phase = 0;

__device__ __forceinline__ ull pk2(float lo, float hi) {
    ull r; asm("mov.b64 %0, {%1, %2};" : "=l"(r) : "f"(lo), "f"(hi)); return r;
}
__device__ __forceinline__ float2 upk2(ull v) {
    float2 r; asm("mov.b64 {%0, %1}, %2;" : "=f"(r.x), "=f"(r.y) : "l"(v)); return r;
}
// packed fp32x2 FMA (2 FMAs/instr; ptxas never auto-fuses this)
__device__ __forceinline__ ull ffma2(ull a, ull b, ull c) {
    ull d; asm("fma.rn.f32x2 %0, %1, %2, %3;" : "=l"(d) : "l"(a), "l"(b), "l"(c)); return d;
}
__device__ __forceinline__ void cpa16(float* s, const float* g) {
    unsigned sa = (unsigned)__cvta_generic_to_shared(s);
    asm volatile("cp.async.cg.shared.global [%0], [%1], 16;" :: "r"(sa), "l"(g));
}
__device__ __forceinline__ void cpcommit() { asm volatile("cp.async.commit_group;"); }
template <int N> __device__ __forceinline__ void cpwait() {
    asm volatile("cp.async.wait_group %0;" :: "n"(N));
}

// ---------------------------------------------------------------------------
// Kernel 1: C[M=32768, N=2048] = x[M,512] * W_ih[N,512]^T + bias
// 128x128 tile, BK=16, 256 threads, 8x8 microtile packed along M (f32x2).
// Stores transposed: xp[(m>>6)][n][m&63].
// ---------------------------------------------------------------------------
__global__ __launch_bounds__(256, 2) void gemm_xproj(
    const float* __restrict__ A, const float* __restrict__ W,
    const float* __restrict__ bih, const float* __restrict__ bhh)
{
    __shared__ float As[16][128];
    __shared__ float Bs[16][128];
    const int tid = threadIdx.x;
    const int m0 = blockIdx.y * 128;
    const int n0 = blockIdx.x * 128;
    const int lrow = tid >> 1;            // 0..127
    const int lc = (tid & 1) * 8;         // k-offset 0 or 8
    const int tm = (tid & 15) * 8;        // m-block (lanes -> consecutive m)
    const int tn = (tid >> 4) * 8;        // n-block

    const float* Ap = A + (size_t)(m0 + lrow) * 512 + lc;
    const float* Bp = W + (size_t)(n0 + lrow) * 512 + lc;

    ull acc[8][4];
#pragma unroll
    for (int j = 0; j < 8; j++)
#pragma unroll
        for (int p = 0; p < 4; p++) acc[j][p] = 0ull;

    // prefetch first k-slab
    float4 a0 = *(const float4*)(Ap);
    float4 a1 = *(const float4*)(Ap + 4);
    float4 b0 = *(const float4*)(Bp);
    float4 b1 = *(const float4*)(Bp + 4);

#pragma unroll 1
    for (int k0 = 0; k0 < 512; k0 += 16) {
        __syncthreads();   // previous compute done before overwriting smem
        As[lc + 0][lrow] = a0.x; As[lc + 1][lrow] = a0.y;
        As[lc + 2][lrow] = a0.z; As[lc + 3][lrow] = a0.w;
        As[lc + 4][lrow] = a1.x; As[lc + 5][lrow] = a1.y;
        As[lc + 6][lrow] = a1.z; As[lc + 7][lrow] = a1.w;
        Bs[lc + 0][lrow] = b0.x; Bs[lc + 1][lrow] = b0.y;
        Bs[lc + 2][lrow] = b0.z; Bs[lc + 3][lrow] = b0.w;
        Bs[lc + 4][lrow] = b1.x; Bs[lc + 5][lrow] = b1.y;
        Bs[lc + 6][lrow] = b1.z; Bs[lc + 7][lrow] = b1.w;
        __syncthreads();
        if (k0 + 16 < 512) {   // prefetch next slab under compute
            a0 = *(const float4*)(Ap + k0 + 16);
            a1 = *(const float4*)(Ap + k0 + 20);
            b0 = *(const float4*)(Bp + k0 + 16);
            b1 = *(const float4*)(Bp + k0 + 20);
        }
#pragma unroll 8
        for (int kk = 0; kk < 16; kk++) {
            float4 av0 = *(const float4*)&As[kk][tm];
            float4 av1 = *(const float4*)&As[kk][tm + 4];
            ull am[4] = { pk2(av0.x, av0.y), pk2(av0.z, av0.w),
                          pk2(av1.x, av1.y), pk2(av1.z, av1.w) };
            float4 bv0 = *(const float4*)&Bs[kk][tn];
            float4 bv1 = *(const float4*)&Bs[kk][tn + 4];
            float bb[8] = { bv0.x, bv0.y, bv0.z, bv0.w, bv1.x, bv1.y, bv1.z, bv1.w };
#pragma unroll
            for (int j = 0; j < 8; j++) {
                ull bd = pk2(bb[j], bb[j]);
#pragma unroll
                for (int p = 0; p < 4; p++) acc[j][p] = ffma2(bd, am[p], acc[j][p]);
            }
        }
    }

#pragma unroll
    for (int j = 0; j < 8; j++) {
        int n = n0 + tn + j;
        float bv = bih[n] + bhh[n];
#pragma unroll
        for (int p = 0; p < 4; p++) {
            float2 v = upk2(acc[j][p]);
            v.x += bv; v.y += bv;
            int m = m0 + tm + 2 * p;
            int tt = m >> 6, bb2 = m & 63;
            *(float2*)&g_xp[((size_t)tt * G4 + n) * Bq + bb2] = v;
        }
    }
}

// ---------------------------------------------------------------------------
// Kernel 2: persistent recurrence. 128 CTAs x 256 threads.
// CTA owns 4 h-columns (16 gate columns). Thread (tb=tid&63, tq=tid>>6)
// owns output (tb, hc0+tq): 4 gate dot-products + elementwise.
// W_hh slice cached in smem for all 512 steps; h staged via cp.async chunks.
// h history lives in d_out itself (step t reads d_out[t-1]).
// ---------------------------------------------------------------------------
__global__ __launch_bounds__(256, 1) void lstm_rec(
    const float* __restrict__ Whh, float* __restrict__ out)
{
    extern __shared__ float sm[];
    float* Ws = sm;                       // [16][512]
    float* hs = sm + 16 * 512;            // [64][HSTRIDE]
    const int tid = threadIdx.x;
    const int tb = tid & 63;
    const int tq = tid >> 6;
    const int hc = blockIdx.x * 4 + tq;

    // load W_hh slice once: smem row r = tq*4+gt  <-  W_hh[gt*512 + hc0 + tq]
    for (int i = tid; i < 16 * 128; i += 256) {
        int r = i >> 7;
        int c4 = i & 127;
        int grow = (r & 3) * 512 + blockIdx.x * 4 + (r >> 2);
        ((float4*)(Ws + r * 512))[c4] = ((const float4*)(Whh + (size_t)grow * 512))[c4];
    }
    unsigned phase = g_phase;   // persisted across replays; uniform (no writes yet)
    __syncthreads();

    const float* wbase = Ws + tq * 4 * 512;
    float cst = 0.f;

#pragma unroll 1
    for (int t = 0; t < Tq; t++) {
        const float* xpt = g_xp + (size_t)t * (G4 * Bq);
        ull acc0 = pk2(xpt[(0 * 512 + hc) * Bq + tb], 0.f);
        ull acc1 = pk2(xpt[(1 * 512 + hc) * Bq + tb], 0.f);
        ull acc2 = pk2(xpt[(2 * 512 + hc) * Bq + tb], 0.f);
        ull acc3 = pk2(xpt[(3 * 512 + hc) * Bq + tb], 0.f);

        if (t > 0) {   // t==0: h=0 -> gates = x_proj, skip matmul entirely
            const float* hp = out + (size_t)(t - 1) * (Bq * Hq);
#pragma unroll
            for (int r = 0; r < 8; r++) {          // issue chunk 0
                int i = tid + r * 256;
                int b = i >> 5, o = (i & 31) * 4;
                cpa16(hs + b * HSTRIDE + o, hp + b * 512 + o);
            }
            cpcommit();
#pragma unroll 1
            for (int c = 0; c < 4; c++) {
                if (c < 3) {                        // issue chunk c+1, wait chunk c
                    int k0 = (c + 1) * 128;
#pragma unroll
                    for (int r = 0; r < 8; r++) {
                        int i = tid + r * 256;
                        int b = i >> 5, o = (i & 31) * 4;
                        cpa16(hs + b * HSTRIDE + k0 + o, hp + b * 512 + k0 + o);
                    }
                    cpcommit();
                    cpwait<1>();
                } else {
                    cpwait<0>();
                }
                __syncthreads();
                const float4* hr = (const float4*)(hs + tb * HSTRIDE + c * 128);
                const float4* w0 = (const float4*)(wbase + 0 * 512 + c * 128);
                const float4* w1 = (const float4*)(wbase + 1 * 512 + c * 128);
                const float4* w2 = (const float4*)(wbase + 2 * 512 + c * 128);
                const float4* w3 = (const float4*)(wbase + 3 * 512 + c * 128);
#pragma unroll 8
                for (int k4 = 0; k4 < 32; k4++) {
                    float4 h4 = hr[k4];
                    ull h01 = pk2(h4.x, h4.y), h23 = pk2(h4.z, h4.w);
                    float4 w;
                    w = w0[k4];
                    acc0 = ffma2(h01, pk2(w.x, w.y), acc0);
                    acc0 = ffma2(h23, pk2(w.z, w.w), acc0);
                    w = w1[k4];
                    acc1 = ffma2(h01, pk2(w.x, w.y), acc1);
                    acc1 = ffma2(h23, pk2(w.z, w.w), acc1);
                    w = w2[k4];
                    acc2 = ffma2(h01, pk2(w.x, w.y), acc2);
                    acc2 = ffma2(h23, pk2(w.z, w.w), acc2);
                    w = w3[k4];
                    acc3 = ffma2(h01, pk2(w.x, w.y), acc3);
                    acc3 = ffma2(h23, pk2(w.z, w.w), acc3);
                }
            }
        }

        float2 v0 = upk2(acc0), v1 = upk2(acc1), v2 = upk2(acc2), v3 = upk2(acc3);
        float gi = v0.x + v0.y, gf = v1.x + v1.y;
        float gg = v2.x + v2.y, go = v3.x + v3.y;
        float iv = 1.f / (1.f + expf(-gi));
        float fv = 1.f / (1.f + expf(-gf));
        float gv = tanhf(gg);
        float ov = 1.f / (1.f + expf(-go));
        cst = fv * cst + iv * gv;
        float hv = ov * tanhf(cst);
        out[(size_t)t * (Bq * Hq) + tb * Hq + hc] = hv;

        if (t < Tq - 1) {
            // -------- software grid barrier (all 128 CTAs co-resident) --------
            __threadfence();
            __syncthreads();
            if (tid == 0) {
                unsigned tgt = phase + 1;
                unsigned old = atomicAdd(&g_count, 1u);
                if (old == REC_NCTA - 1) {
                    g_count = 0;
                    __threadfence();
                    g_phase = tgt;
                } else {
                    while (g_phase != tgt) { }
                    __threadfence();
                }
            }
            __syncthreads();
            phase++;
        }
    }
}

extern "C" void kernel_launch(void* const* d_in, const int* in_sizes, int n_in,
                              void* d_out, int out_size) {
    const float* x   = (const float*)d_in[0];   // [512,64,512]
    const float* Wih = (const float*)d_in[1];   // [2048,512]
    const float* Whh = (const float*)d_in[2];   // [2048,512]
    const float* bih = (const float*)d_in[3];   // [2048]
    const float* bhh = (const float*)d_in[4];   // [2048]
    float* out = (float*)d_out;                 // [512,64,512]

    cudaFuncSetAttribute(lstm_rec, cudaFuncAttributeMaxDynamicSharedMemorySize, REC_SMEM);

    dim3 g1(G4 / 128, (Tq * Bq) / 128);         // (16, 256)
    gemm_xproj<<<g1, 256>>>(x, Wih, bih, bhh);
    lstm_rec<<<REC_NCTA, 256, REC_SMEM>>>(Whh, out);
}

// round 2
// speedup vs baseline: 1.3895x; 1.3895x over previous
#include <cuda_runtime.h>
#include <math.h>

// LSTM: T=512, B=64, I=H=512.  out[t,b,h] = h_t.
// Kernel 1: x_proj[t][g*512+h][b] = x @ W_ih^T + (b_ih + b_hh)
// Kernel 2: persistent 128-CTA recurrent kernel, software grid barrier.

#define Tq 512
#define Bq 64
#define Hq 512
#define G4 2048
#define REC_NCTA 128
#define HSTRIDE 516  // 516 % 32 == 4 -> conflict-free float4 rows (8-lane phases)

typedef unsigned long long ull;

__device__ float g_xp[(size_t)Tq * G4 * Bq];   // 256MB scratch
__device__ unsigned g_count = 0;               // monotonic barrier counter

__device__ __forceinline__ ull pk2(float lo, float hi) {
    ull r; asm("mov.b64 %0, {%1, %2};" : "=l"(r) : "f"(lo), "f"(hi)); return r;
}
__device__ __forceinline__ float2 upk2(ull v) {
    float2 r; asm("mov.b64 {%0, %1}, %2;" : "=f"(r.x), "=f"(r.y) : "l"(v)); return r;
}
__device__ __forceinline__ ull ffma2(ull a, ull b, ull c) {
    ull d; asm("fma.rn.f32x2 %0, %1, %2, %3;" : "=l"(d) : "l"(a), "l"(b), "l"(c)); return d;
}
__device__ __forceinline__ void cpa16(float* s, const float* g) {
    unsigned sa = (unsigned)__cvta_generic_to_shared(s);
    asm volatile("cp.async.cg.shared.global [%0], [%1], 16;" :: "r"(sa), "l"(g));
}
__device__ __forceinline__ void cpcommit() { asm volatile("cp.async.commit_group;"); }
template <int N> __device__ __forceinline__ void cpwait() {
    asm volatile("cp.async.wait_group %0;" :: "n"(N));
}
__device__ __forceinline__ float sigf(float x) {
    return __fdividef(1.f, 1.f + __expf(-x));
}
__device__ __forceinline__ float tanhx(float x) {
    return __fdividef(2.f, 1.f + __expf(-2.f * x)) - 1.f;
}

// ---------------------------------------------------------------------------
// Kernel 1: C[M=32768, N=2048] = x[M,512] * W_ih[N,512]^T + bias
// 128x128 tile, BK=16, 256 threads, 8x8 microtile (two consecutive-4 chunks).
// ---------------------------------------------------------------------------
__global__ __launch_bounds__(256, 2) void gemm_xproj(
    const float* __restrict__ A, const float* __restrict__ W,
    const float* __restrict__ bih, const float* __restrict__ bhh)
{
    __shared__ float As[16][128];
    __shared__ float Bs[16][128];
    const int tid = threadIdx.x;
    const int m0 = blockIdx.y * 128;
    const int n0 = blockIdx.x * 128;
    const int lrow = tid >> 1;
    const int lc = (tid & 1) * 8;
    const int tmq = tid & 15;            // m chunk: floats [tmq*4, +4) and +64
    const int tn = (tid >> 4) * 8;

    const float* Ap = A + (size_t)(m0 + lrow) * 512 + lc;
    const float* Bp = W + (size_t)(n0 + lrow) * 512 + lc;

    ull acc[8][4];
#pragma unroll
    for (int j = 0; j < 8; j++)
#pragma unroll
        for (int p = 0; p < 4; p++) acc[j][p] = 0ull;

    float4 a0 = *(const float4*)(Ap);
    float4 a1 = *(const float4*)(Ap + 4);
    float4 b0 = *(const float4*)(Bp);
    float4 b1 = *(const float4*)(Bp + 4);

    const float4* As4 = (const float4*)As;
    const float4* Bs4 = (const float4*)Bs;

#pragma unroll 1
    for (int k0 = 0; k0 < 512; k0 += 16) {
        __syncthreads();
        As[lc + 0][lrow] = a0.x; As[lc + 1][lrow] = a0.y;
        As[lc + 2][lrow] = a0.z; As[lc + 3][lrow] = a0.w;
        As[lc + 4][lrow] = a1.x; As[lc + 5][lrow] = a1.y;
        As[lc + 6][lrow] = a1.z; As[lc + 7][lrow] = a1.w;
        Bs[lc + 0][lrow] = b0.x; Bs[lc + 1][lrow] = b0.y;
        Bs[lc + 2][lrow] = b0.z; Bs[lc + 3][lrow] = b0.w;
        Bs[lc + 4][lrow] = b1.x; Bs[lc + 5][lrow] = b1.y;
        Bs[lc + 6][lrow] = b1.z; Bs[lc + 7][lrow] = b1.w;
        __syncthreads();
        if (k0 + 16 < 512) {
            a0 = *(const float4*)(Ap + k0 + 16);
            a1 = *(const float4*)(Ap + k0 + 20);
            b0 = *(const float4*)(Bp + k0 + 16);
            b1 = *(const float4*)(Bp + k0 + 20);
        }
#pragma unroll 8
        for (int kk = 0; kk < 16; kk++) {
            float4 av0 = As4[kk * 32 + tmq];          // m: tmq*4 .. +3
            float4 av1 = As4[kk * 32 + 16 + tmq];     // m: tmq*4+64 .. +3
            ull am[4] = { pk2(av0.x, av0.y), pk2(av0.z, av0.w),
                          pk2(av1.x, av1.y), pk2(av1.z, av1.w) };
            float4 bv0 = Bs4[kk * 32 + (tid >> 4) * 2];
            float4 bv1 = Bs4[kk * 32 + (tid >> 4) * 2 + 1];
            float bb[8] = { bv0.x, bv0.y, bv0.z, bv0.w, bv1.x, bv1.y, bv1.z, bv1.w };
#pragma unroll
            for (int j = 0; j < 8; j++) {
                ull bd = pk2(bb[j], bb[j]);
#pragma unroll
                for (int p = 0; p < 4; p++) acc[j][p] = ffma2(bd, am[p], acc[j][p]);
            }
        }
    }

#pragma unroll
    for (int j = 0; j < 8; j++) {
        int n = n0 + tn + j;
        float bv = bih[n] + bhh[n];
#pragma unroll
        for (int p = 0; p < 4; p++) {
            float2 v = upk2(acc[j][p]);
            v.x += bv; v.y += bv;
            int m = m0 + tmq * 4 + (p & 1) * 2 + (p >> 1) * 64;
            int tt = m >> 6, bb2 = m & 63;
            *(float2*)&g_xp[((size_t)tt * G4 + n) * Bq + bb2] = v;
        }
    }
}

// ---------------------------------------------------------------------------
// Kernel 2: persistent recurrence. 128 CTAs x 256 threads.
// Compute role: lane = (b4 = lane&15, hcl = lane>>4); warp = (kq = w&3, hcp = w>>2)
//   thread computes partial gates for b in {b4,b4+16,b4+32,b4+48}, hc-local
//   hcL = hcp*2+hcl, gates 0..3, K-slice kq*128..+128.  (w-loads: 2 addrs/warp,
//   h-loads: 16 addrs/warp -> crossbar == FMA floor.)
// Reduce/elementwise role: thread tid = (eb = tid&63, ehc = tid>>6) owns one
//   (b,hc) output + its c-state; sums 4 kq partials + x_proj.
// ---------------------------------------------------------------------------
__global__ __launch_bounds__(256, 1) void lstm_rec(
    const float* __restrict__ Whh, float* __restrict__ out)
{
    extern __shared__ float sm[];
    float* Ws = sm;                         // [16 rows=(hcL*4+g)][512]
    float* hs = sm + 16 * 512;              // [64][HSTRIDE]
    float* ps = hs + 64 * HSTRIDE;          // [4 kq][4 hcL][4 g][64 b]
    const int tid = threadIdx.x;
    const int lane = tid & 31;
    const int warp = tid >> 5;
    const int b4 = lane & 15;
    const int hcl = lane >> 4;
    const int kq = warp & 3;
    const int hcp = warp >> 2;
    const int hcL = hcp * 2 + hcl;
    const int eb = tid & 63;
    const int ehc = tid >> 6;
    const int hcE = blockIdx.x * 4 + ehc;

    // load W_hh slice: Ws row r = hcL*4+g  <-  Whh[g*512 + blockIdx.x*4 + hcL]
    for (int i = tid; i < 16 * 128; i += 256) {
        int r = i >> 7;
        int c4 = i & 127;
        int grow = (r & 3) * 512 + blockIdx.x * 4 + (r >> 2);
        ((float4*)(Ws + r * 512))[c4] = ((const float4*)(Whh + (size_t)grow * 512))[c4];
    }
    __syncthreads();

    const float4* wb = (const float4*)Ws + (hcL * 4) * 128 + kq * 32;
    const float4* hb = (const float4*)hs;   // row stride 129 float4
    float cst = 0.f;

#pragma unroll 1
    for (int t = 0; t < Tq; t++) {
        // x_proj for this step (consumed late, at reduction)
        const float* xpt = g_xp + (size_t)t * (G4 * Bq) + (size_t)hcE * Bq + eb;
        float xv0 = __ldg(xpt + 0 * 512 * Bq);
        float xv1 = __ldg(xpt + 1 * 512 * Bq);
        float xv2 = __ldg(xpt + 2 * 512 * Bq);
        float xv3 = __ldg(xpt + 3 * 512 * Bq);

        if (t > 0) {
            // stage h[t-1] (128KB) into smem
            const float* hp = out + (size_t)(t - 1) * (Bq * Hq);
#pragma unroll
            for (int j = 0; j < 32; j++) {
                int idx = tid + j * 256;          // float4 index, 8192 total
                int row = idx >> 7, c4 = idx & 127;
                cpa16(hs + row * HSTRIDE + c4 * 4, hp + row * 512 + c4 * 4);
            }
            cpcommit();
            cpwait<0>();
            __syncthreads();

            ull acc[4][4];
#pragma unroll
            for (int b = 0; b < 4; b++)
#pragma unroll
                for (int g = 0; g < 4; g++) acc[b][g] = 0ull;

#pragma unroll 4
            for (int k4 = 0; k4 < 32; k4++) {
                float4 w0 = wb[0 * 128 + k4];
                float4 w1 = wb[1 * 128 + k4];
                float4 w2 = wb[2 * 128 + k4];
                float4 w3 = wb[3 * 128 + k4];
                ull w0a = pk2(w0.x, w0.y), w0b = pk2(w0.z, w0.w);
                ull w1a = pk2(w1.x, w1.y), w1b = pk2(w1.z, w1.w);
                ull w2a = pk2(w2.x, w2.y), w2b = pk2(w2.z, w2.w);
                ull w3a = pk2(w3.x, w3.y), w3b = pk2(w3.z, w3.w);
#pragma unroll
                for (int b = 0; b < 4; b++) {
                    float4 h4 = hb[(b4 + 16 * b) * 129 + kq * 32 + k4];
                    ull h01 = pk2(h4.x, h4.y), h23 = pk2(h4.z, h4.w);
                    acc[b][0] = ffma2(h01, w0a, acc[b][0]);
                    acc[b][1] = ffma2(h01, w1a, acc[b][1]);
                    acc[b][2] = ffma2(h01, w2a, acc[b][2]);
                    acc[b][3] = ffma2(h01, w3a, acc[b][3]);
                    acc[b][0] = ffma2(h23, w0b, acc[b][0]);
                    acc[b][1] = ffma2(h23, w1b, acc[b][1]);
                    acc[b][2] = ffma2(h23, w2b, acc[b][2]);
                    acc[b][3] = ffma2(h23, w3b, acc[b][3]);
                }
            }
            // fold f32x2 halves, store partials
#pragma unroll
            for (int b = 0; b < 4; b++)
#pragma unroll
                for (int g = 0; g < 4; g++) {
                    float2 v = upk2(acc[b][g]);
                    ps[((kq * 4 + hcL) * 4 + g) * 64 + b4 + 16 * b] = v.x + v.y;
                }
        }
        __syncthreads();

        // reduction + elementwise (every thread owns one (eb, ehc))
        float g0 = xv0, g1 = xv1, g2 = xv2, g3 = xv3;
        if (t > 0) {
#pragma unroll
            for (int q = 0; q < 4; q++) {
                const float* pq = ps + ((q * 4 + ehc) * 4) * 64 + eb;
                g0 += pq[0 * 64];
                g1 += pq[1 * 64];
                g2 += pq[2 * 64];
                g3 += pq[3 * 64];
            }
        }
        float iv = sigf(g0);
        float fv = sigf(g1);
        float gv = tanhx(g2);
        float ov = sigf(g3);
        cst = fv * cst + iv * gv;
        float hv = ov * tanhx(cst);
        out[(size_t)t * (Bq * Hq) + eb * Hq + hcE] = hv;

        if (t < Tq - 1) {
            __syncthreads();           // all STG issued before arrive
            if (tid == 0) {
                unsigned old;
                asm volatile("atom.release.gpu.add.u32 %0, [%1], 1;"
                             : "=r"(old) : "l"(&g_count) : "memory");
                unsigned target = (unsigned)REC_NCTA * (unsigned)(t + 1);
                unsigned v = old + 1;
                while (v < target) {
                    asm volatile("ld.acquire.gpu.u32 %0, [%1];"
                                 : "=r"(v) : "l"(&g_count) : "memory");
                }
            }
            __syncthreads();
        }
    }

    // final arrive: last CTA resets the counter for the next graph replay
    if (tid == 0) {
        unsigned old = atomicAdd(&g_count, 1u);
        if (old == (unsigned)REC_NCTA * (unsigned)Tq - 1u)
            *((volatile unsigned*)&g_count) = 0u;
    }
}

#define REC_SMEM ((16 * 512 + 64 * HSTRIDE + 4 * 4 * 4 * 64) * 4)

extern "C" void kernel_launch(void* const* d_in, const int* in_sizes, int n_in,
                              void* d_out, int out_size) {
    const float* x   = (const float*)d_in[0];   // [512,64,512]
    const float* Wih = (const float*)d_in[1];   // [2048,512]
    const float* Whh = (const float*)d_in[2];   // [2048,512]
    const float* bih = (const float*)d_in[3];   // [2048]
    const float* bhh = (const float*)d_in[4];   // [2048]
    float* out = (float*)d_out;                 // [512,64,512]

    cudaFuncSetAttribute(lstm_rec, cudaFuncAttributeMaxDynamicSharedMemorySize, REC_SMEM);

    dim3 g1(G4 / 128, (Tq * Bq) / 128);         // (16, 256)
    gemm_xproj<<<g1, 256>>>(x, Wih, bih, bhh);
    lstm_rec<<<REC_NCTA, 256, REC_SMEM>>>(Whh, out);
}